// round 17
// baseline (speedup 1.0000x reference)
#include <cuda_runtime.h>
#include <cuda_fp16.h>
#include <math.h>
#include <stdint.h>

// Problem dims (fixed per reference)
#define Bdim 32
#define Sdim 2048
#define Ddim 1024
#define Udim 1024
#define BS   (Bdim * Sdim)   // 65536 rows of the big GEMM

// ---- device scratch (no cudaMalloc allowed) ----
__device__ float g_dec_p[Bdim * Udim];            // [B,U]
__device__ float g_scores[Bdim * Sdim];           // [B,S]
__device__ float g_wpart[8 * Bdim * Ddim];        // s-split partials of attn-weighted h_enc
__device__ __half g_Ahi[(size_t)BS * Ddim];       // h_enc fp16 (128MB)
__device__ __half g_Bhi[(size_t)Udim * Ddim];     // W_enc^T fp16 [u][d]

// ============================================================================
// PTX helpers (portable sm_80-level ISA: cp.async / ldmatrix / mma.sync)
// ============================================================================
__device__ __forceinline__ uint32_t smem_to_u32(const void* p) {
    uint32_t a;
    asm("{ .reg .u64 t; cvta.to.shared.u64 t, %1; cvt.u32.u64 %0, t; }" : "=r"(a) : "l"(p));
    return a;
}
#define CP_ASYNC16(dst, src) \
    asm volatile("cp.async.cg.shared.global [%0], [%1], 16;" :: "r"(dst), "l"(src) : "memory")
#define CP_COMMIT() asm volatile("cp.async.commit_group;" ::: "memory")
#define CP_WAIT2()  asm volatile("cp.async.wait_group 2;" ::: "memory")
#define CP_WAIT1()  asm volatile("cp.async.wait_group 1;" ::: "memory")
#define CP_WAIT0()  asm volatile("cp.async.wait_group 0;" ::: "memory")

__device__ __forceinline__ void ldsm4(uint32_t* r, uint32_t addr) {
    asm volatile("ldmatrix.sync.aligned.m8n8.x4.shared.b16 {%0,%1,%2,%3}, [%4];"
                 : "=r"(r[0]), "=r"(r[1]), "=r"(r[2]), "=r"(r[3]) : "r"(addr));
}
// D(f32) += A(f16,4regs) * B(f16,2regs)   m16n8k16 row.col
__device__ __forceinline__ void mma_f16(float* d, const uint32_t* a, uint32_t b0, uint32_t b1) {
    asm volatile(
        "mma.sync.aligned.m16n8k16.row.col.f32.f16.f16.f32 "
        "{%0,%1,%2,%3}, {%4,%5,%6,%7}, {%8,%9}, {%0,%1,%2,%3};"
        : "+f"(d[0]), "+f"(d[1]), "+f"(d[2]), "+f"(d[3])
        : "r"(a[0]), "r"(a[1]), "r"(a[2]), "r"(a[3]), "r"(b0), "r"(b1));
}

// fast tanh: 1 - 2/(e^{2x}+1). MUFU.EX2 + MUFU.RCP, ~1e-6 abs err.
__device__ __forceinline__ float tanh_fast(float x) {
    float e = __expf(2.0f * x);
    return 1.0f - __fdividef(2.0f, e + 1.0f);
}

// ============================================================================
// Kernel 0a: convert h_enc -> fp16 (same layout)
// ============================================================================
__global__ __launch_bounds__(256) void conv_h_kernel(const float* __restrict__ src) {
    size_t i = ((size_t)blockIdx.x * 256 + threadIdx.x) * 4;
    float4 v = *reinterpret_cast<const float4*>(src + i);
    *reinterpret_cast<__half2*>(g_Ahi + i)     = __floats2half2_rn(v.x, v.y);
    *reinterpret_cast<__half2*>(g_Ahi + i + 2) = __floats2half2_rn(v.z, v.w);
}

// ============================================================================
// Kernel 0b: W_enc [D,U] -> transposed fp16 [U,D]
// ============================================================================
__global__ __launch_bounds__(256) void conv_w_kernel(const float* __restrict__ W) {
    __shared__ float s[32][33];
    int tx = threadIdx.x, ty = threadIdx.y;     // 32 x 8
    int u0 = blockIdx.x * 32, d0 = blockIdx.y * 32;
    #pragma unroll
    for (int k = 0; k < 4; ++k)
        s[ty + k * 8][tx] = W[(size_t)(d0 + ty + k * 8) * Udim + u0 + tx];
    __syncthreads();
    #pragma unroll
    for (int k = 0; k < 4; ++k) {
        float v = s[tx][ty + k * 8];
        g_Bhi[(size_t)(u0 + ty + k * 8) * Ddim + d0 + tx] = __float2half_rn(v);
    }
}

// ============================================================================
// Kernel 1: dec_p[b,u] = b_dec[u] + sum_d h_dec[b,d] * W_dec[d,u]
// ============================================================================
__global__ __launch_bounds__(256) void decp_kernel(const float* __restrict__ h_dec,
                                                   const float* __restrict__ W_dec,
                                                   const float* __restrict__ b_dec) {
    __shared__ float hv[Ddim];
    const int b = blockIdx.x;
    const int u = blockIdx.y * 256 + threadIdx.x;
    for (int d = threadIdx.x; d < Ddim; d += 256) hv[d] = h_dec[b * Ddim + d];
    __syncthreads();
    float acc = b_dec[u];
    #pragma unroll 8
    for (int d = 0; d < Ddim; ++d) acc = fmaf(hv[d], W_dec[d * Udim + u], acc);
    g_dec_p[b * Udim + u] = acc;
}

// ============================================================================
// Kernel 2: score GEMM via mma.sync fp16 + fused tanh/W_com epilogue.
// CTA tile 128 x 256 (4 n-groups over U). 512 threads = 16 warps of 32x64
// (wm=wid&3 -> rows wm*32, wn=wid>>2 -> cols wn*64). BK=32. Flat 128-iter
// mainloop, 4-stage cp.async (3-deep), ONE barrier/iter. 4 warps/SMSP for
// latency hiding; 64 accumulator floats/thread -> fits 128-reg cap.
// ============================================================================
#define A_BYTES  10240u                 // 128 rows * 80B
#define B_BYTES  20480u                 // 256 rows * 80B
#define STG_BYTES (A_BYTES + B_BYTES)   // 30720
#define NSTG 4
#define OFF_DECW (NSTG * STG_BYTES)     // 122880: float2[1024] = 8192
#define OFF_RED  (OFF_DECW + 8192u)     // float[128][4] = 2048
#define SMEM_SCORE (OFF_RED + 2048u)    // 133120
#define NTHREADS 512

struct LoadCtx {
    const __half* srcA;      // per-thread A base (row0,r,seg folded in)
    const __half* srcB[2];   // per-thread B base (r,seg folded in)
    uint32_t dstA;           // smem offsets relative to stage base
    uint32_t dstB[2];
};

__device__ __forceinline__ void score_loads(const LoadCtx& c, int t, uint32_t sbase) {
    const uint32_t stg = sbase + (uint32_t)(t & (NSTG - 1)) * STG_BYTES;
    const uint32_t aoff = (uint32_t)((t & 31) << 5);               // kt*32 elements
    const uint32_t boff = (uint32_t)((t >> 5) << 18) | aoff;       // ng*256*1024 + kt*32
    CP_ASYNC16(stg + c.dstA, c.srcA + aoff);
    #pragma unroll
    for (int k = 0; k < 2; ++k) CP_ASYNC16(stg + c.dstB[k], c.srcB[k] + boff);
}

__global__ __launch_bounds__(NTHREADS, 1) void score_mma_kernel(const float* __restrict__ W_com,
                                                                const float* __restrict__ b_com,
                                                                const float* __restrict__ b_enc) {
    extern __shared__ char sm[];
    const uint32_t sbase = smem_to_u32(sm);
    float2* decw = reinterpret_cast<float2*>(sm + OFF_DECW);
    float* red   = reinterpret_cast<float*>(sm + OFF_RED);

    const int tid  = threadIdx.x;
    const int wid  = tid >> 5, lane = tid & 31;
    const int wm   = wid & 3;           // rows wm*32
    const int wn   = wid >> 2;          // cols wn*64 (0..3)
    const int row0 = blockIdx.x * 128;
    const int b    = row0 >> 11;

    // ---- hoisted per-thread load addressing ----
    LoadCtx c;
    {
        int r = tid >> 2, seg = tid & 3;           // A: r 0..127
        c.srcA = g_Ahi + (((size_t)(row0 + r)) << 10) + (seg << 3);
        c.dstA = (uint32_t)(r * 80 + seg * 16);
    }
    #pragma unroll
    for (int k = 0; k < 2; ++k) {
        int idx = tid + k * NTHREADS;
        int r = idx >> 2, seg = idx & 3;           // B: r 0..255
        c.srcB[k] = g_Bhi + (((size_t)r) << 10) + (seg << 3);
        c.dstB[k] = A_BYTES + (uint32_t)(r * 80 + seg * 16);
    }

    // 3-deep prefetch while decw fills
    score_loads(c, 0, sbase);
    CP_COMMIT();
    score_loads(c, 1, sbase);
    CP_COMMIT();
    score_loads(c, 2, sbase);
    CP_COMMIT();

    for (int i = tid; i < Udim; i += NTHREADS)
        decw[i] = make_float2(g_dec_p[b * Udim + i] + b_enc[i], W_com[i]);

    float rs[4];
    #pragma unroll
    for (int i = 0; i < 4; ++i) rs[i] = 0.f;
    float acc[2][8][4];
    const uint32_t lrow = (uint32_t)(lane & 15) * 80u + ((uint32_t)(lane >> 4) << 4);
    const uint32_t aOff = (uint32_t)(wm * 32) * 80u + lrow;
    const uint32_t bOff = A_BYTES + (uint32_t)(wn * 64) * 80u + lrow;

    #pragma unroll 1
    for (int t = 0; t < 128; ++t) {
        const int kt = t & 31;
        if (kt == 0) {
            #pragma unroll
            for (int mi = 0; mi < 2; ++mi)
                #pragma unroll
                for (int nj = 0; nj < 8; ++nj)
                    #pragma unroll
                    for (int e = 0; e < 4; ++e) acc[mi][nj][e] = 0.f;
        }
        if (t < 126) { CP_WAIT2(); } else if (t == 126) { CP_WAIT1(); } else { CP_WAIT0(); }
        __syncthreads();
        if (t + 3 < 128) {
            score_loads(c, t + 3, sbase);
            CP_COMMIT();
        }

        const uint32_t stg = sbase + (uint32_t)(t & (NSTG - 1)) * STG_BYTES;
        const uint32_t sA = stg + aOff;
        const uint32_t sB = stg + bOff;
        #pragma unroll
        for (int ks = 0; ks < 2; ++ks) {
            uint32_t ah[2][4];
            #pragma unroll
            for (int mi = 0; mi < 2; ++mi)
                ldsm4(ah[mi], sA + (uint32_t)(mi * 16) * 80u + (uint32_t)(ks * 32));
            #pragma unroll
            for (int p = 0; p < 4; ++p) {
                uint32_t bh[4];
                ldsm4(bh, sB + (uint32_t)(p * 16) * 80u + (uint32_t)(ks * 32));
                #pragma unroll
                for (int mi = 0; mi < 2; ++mi) {
                    mma_f16(acc[mi][2 * p],     ah[mi], bh[0], bh[2]);
                    mma_f16(acc[mi][2 * p + 1], ah[mi], bh[1], bh[3]);
                }
            }
        }

        if (kt == 31) {
            // epilogue: x = enc_p + (dec_p + b_enc); rs += W_com * tanh(x)
            const int ng = t >> 5;
            #pragma unroll
            for (int mi = 0; mi < 2; ++mi) {
                #pragma unroll
                for (int nj = 0; nj < 8; ++nj) {
                    int u = ng * 256 + wn * 64 + nj * 8 + 2 * (lane & 3);
                    float2 w0 = decw[u];
                    float2 w1 = decw[u + 1];
                    rs[2 * mi] += w0.y * tanh_fast(acc[mi][nj][0] + w0.x) +
                                  w1.y * tanh_fast(acc[mi][nj][1] + w1.x);
                    rs[2 * mi + 1] += w0.y * tanh_fast(acc[mi][nj][2] + w0.x) +
                                      w1.y * tanh_fast(acc[mi][nj][3] + w1.x);
                }
            }
        }
    }

    // reduce the 4-lane quads (cols) that share a row
    #pragma unroll
    for (int i = 0; i < 4; ++i) {
        rs[i] += __shfl_xor_sync(0xffffffffu, rs[i], 1);
        rs[i] += __shfl_xor_sync(0xffffffffu, rs[i], 2);
    }
    if ((lane & 3) == 0) {
        #pragma unroll
        for (int mi = 0; mi < 2; ++mi)
            #pragma unroll
            for (int h = 0; h < 2; ++h) {
                int row = wm * 32 + mi * 16 + h * 8 + (lane >> 2);
                red[row * 4 + wn] = rs[2 * mi + h];
            }
    }
    __syncthreads();
    if (tid < 128)
        g_scores[row0 + tid] = red[tid * 4] + red[tid * 4 + 1] + red[tid * 4 + 2] +
                               red[tid * 4 + 3] + __ldg(&b_com[0]);
}

// ============================================================================
// Kernel 3: softmax over S per batch
// ============================================================================
__global__ __launch_bounds__(256) void softmax_kernel(float* __restrict__ attn_out) {
    __shared__ float sm[256];
    const int b = blockIdx.x;
    const int tid = threadIdx.x;
    float v[8];
    float mx = -3.4e38f;
    #pragma unroll
    for (int i = 0; i < 8; ++i) {
        v[i] = g_scores[b * Sdim + tid + i * 256];
        mx = fmaxf(mx, v[i]);
    }
    sm[tid] = mx;
    __syncthreads();
    for (int off = 128; off > 0; off >>= 1) {
        if (tid < off) sm[tid] = fmaxf(sm[tid], sm[tid + off]);
        __syncthreads();
    }
    const float m = sm[0];
    __syncthreads();
    float sum = 0.f;
    #pragma unroll
    for (int i = 0; i < 8; ++i) {
        v[i] = expf(v[i] - m);
        sum += v[i];
    }
    sm[tid] = sum;
    __syncthreads();
    for (int off = 128; off > 0; off >>= 1) {
        if (tid < off) sm[tid] += sm[tid + off];
        __syncthreads();
    }
    const float inv = 1.f / sm[0];
    #pragma unroll
    for (int i = 0; i < 8; ++i) attn_out[b * Sdim + tid + i * 256] = v[i] * inv;
}

// ============================================================================
// Kernel 4: weighted[b,d] = sum_s attn[b,s] * h_enc_fp16[b,s,d] (8 s-splits,
// reads the fp16 copy: half the traffic)
// ============================================================================
__global__ __launch_bounds__(256) void weighted_kernel(const float* __restrict__ attn) {
    const int b = blockIdx.x;
    const int d4 = threadIdx.x;          // 256 threads x 4 halves = 1024
    const int spl = blockIdx.y;
    const int s0 = spl * (Sdim / 8);
    const uint2* base =
        reinterpret_cast<const uint2*>(g_Ahi + (((size_t)b * Sdim + s0) << 10)) + d4;
    const float* av = attn + b * Sdim + s0;
    float4 acc = make_float4(0.f, 0.f, 0.f, 0.f);
    #pragma unroll 4
    for (int s = 0; s < Sdim / 8; ++s) {
        float a = __ldg(av + s);
        uint2 v = base[(size_t)s * (Ddim / 4)];
        float2 f01 = __half22float2(*reinterpret_cast<__half2*>(&v.x));
        float2 f23 = __half22float2(*reinterpret_cast<__half2*>(&v.y));
        acc.x = fmaf(a, f01.x, acc.x);
        acc.y = fmaf(a, f01.y, acc.y);
        acc.z = fmaf(a, f23.x, acc.z);
        acc.w = fmaf(a, f23.y, acc.w);
    }
    *reinterpret_cast<float4*>(g_wpart + (size_t)(spl * Bdim + b) * Ddim + d4 * 4) = acc;
}

// ============================================================================
// Kernel 5: context[b,u] = b_enc[u] + sum_d weighted[b,d] * W_enc[d,u]
// ============================================================================
__global__ __launch_bounds__(256) void context_kernel(const float* __restrict__ W_enc,
                                                      const float* __restrict__ b_enc,
                                                      float* __restrict__ out_ctx) {
    __shared__ float wv[Ddim];
    const int b = blockIdx.x;
    const int u = blockIdx.y * 256 + threadIdx.x;
    for (int d = threadIdx.x; d < Ddim; d += 256) {
        float s = 0.f;
        #pragma unroll
        for (int p = 0; p < 8; ++p) s += g_wpart[(p * Bdim + b) * Ddim + d];
        wv[d] = s;
    }
    __syncthreads();
    float acc = b_enc[u];
    #pragma unroll 8
    for (int d = 0; d < Ddim; ++d) acc = fmaf(wv[d], W_enc[d * Udim + u], acc);
    out_ctx[b * Udim + u] = acc;
}

// ============================================================================
extern "C" void kernel_launch(void* const* d_in, const int* in_sizes, int n_in,
                              void* d_out, int out_size) {
    const float* h_enc = (const float*)d_in[0];
    const float* h_dec = (const float*)d_in[1];
    const float* W_enc = (const float*)d_in[2];
    const float* b_enc = (const float*)d_in[3];
    const float* W_dec = (const float*)d_in[4];
    const float* b_dec = (const float*)d_in[5];
    const float* W_com = (const float*)d_in[6];
    const float* b_com = (const float*)d_in[7];

    float* out = (float*)d_out;
    float* out_ctx = out;                 // [B,U]
    float* out_attn = out + Bdim * Udim;  // [B,S,1]

    cudaFuncSetAttribute(score_mma_kernel, cudaFuncAttributeMaxDynamicSharedMemorySize,
                         SMEM_SCORE);

    conv_h_kernel<<<(BS * Ddim) / (256 * 4), 256>>>(h_enc);
    conv_w_kernel<<<dim3(Udim / 32, Ddim / 32), dim3(32, 8)>>>(W_enc);
    decp_kernel<<<dim3(Bdim, Udim / 256), 256>>>(h_dec, W_dec, b_dec);
    score_mma_kernel<<<BS / 128, NTHREADS, SMEM_SCORE>>>(W_com, b_com, b_enc);
    softmax_kernel<<<Bdim, 256>>>(out_attn);
    weighted_kernel<<<dim3(Bdim, 8), 256>>>(out_attn);
    context_kernel<<<dim3(Bdim, Udim / 256), 256>>>(W_enc, b_enc, out_ctx);
}